// round 10
// baseline (speedup 1.0000x reference)
#include <cuda_runtime.h>
#include <cuda_bf16.h>
#include <cstdint>
#include <math.h>

// ---------------- problem constants ----------------
#define S_    3
#define B_    1024
#define D_    64
#define H_    128
#define O_    128
#define T_    64
#define NROW  3072                    // S_*B_
#define NELEM (NROW * D_)             // 196608
#define RTOL_ 1e-4f
#define ATOL_ 1e-5f
#define MAX_INNER 12

// ---------------- kernel config ----------------
#define NCTA 128
#define TPB  256                      // 8 warps, 2 per SMSP
#define NW_  8
#define RPC  24                       // rows per CTA
#define RPG  6                        // rows per warp-pair group
#define RPB  3                        // stage-B rows per warp

typedef unsigned long long u64;

// ---------------- packed f32x2 helpers ----------------
__device__ __forceinline__ u64 ffma2(u64 a, u64 b, u64 c) {
    u64 d; asm("fma.rn.f32x2 %0, %1, %2, %3;" : "=l"(d) : "l"(a), "l"(b), "l"(c)); return d;
}
__device__ __forceinline__ u64 dup2(float v) {
    u64 r; asm("mov.b64 %0, {%1, %1};" : "=l"(r) : "f"(v)); return r;
}
__device__ __forceinline__ float2 u2f2(u64 v) {
    float2 f; asm("mov.b64 {%0, %1}, %2;" : "=f"(f.x), "=f"(f.y) : "l"(v)); return f;
}
__device__ __forceinline__ float ulo(u64 v) {
    float a, b; asm("mov.b64 {%0, %1}, %2;" : "=f"(a), "=f"(b) : "l"(v)); return a;
}
__device__ __forceinline__ void bar_pair(int g) {
    asm volatile("bar.sync %0, %1;" :: "r"(g + 1), "r"(64) : "memory");
}

// ---------------- shared memory layout ----------------
// Y/Yt/Y5/H are stored DUPLICATED: element [r][d] = {v, v} as u64, so FFMA2
// broadcast operands come straight from LDS (no dup2 movs). K stays plain.
struct __align__(16) Smem {
    float W1[D_][H_];        // 32 KB (d-major)
    float W2[H_][D_];        // 32 KB (j-major)
    float b1[H_];
    float b2[D_];
    u64 Yd [RPC][D_];        // 12 KB
    u64 Y5d[RPC][D_];        // 12 KB
    u64 Ytd[RPC][D_];        // 12 KB
    u64 Hd [RPC][H_];        // 24 KB
    float K [7][RPC][D_];    // 42 KB
    float red[NW_];
    float s_ratio;
};
#define SMEM_BYTES ((int)sizeof(Smem))

// ---------------- device globals (scratch; no allocations allowed) ----------------
__device__ unsigned g_bar = 0;                         // monotone barrier counter
__device__ float    g_part[2][NCTA];                   // per-CTA partial err sums
__device__ float    g_sol[(size_t)NROW * T_ * D_];     // fallback sol_z scratch

// ---------------- grid-wide barrier (launch-agnostic, all CTAs co-resident) ------
__device__ __forceinline__ void grid_barrier(int tid) {
    __syncthreads();
    if (tid == 0) {
        __threadfence();
        unsigned arrival = atomicAdd(&g_bar, 1u);
        unsigned target = arrival - (arrival % NCTA) + NCTA;
        while ((int)(*(volatile unsigned*)&g_bar - target) < 0) {
            __nanosleep(32);
        }
        __threadfence();
    }
    __syncthreads();
}

// ---------------- f(Yind) -> Kout ------------------------------------------------
// group g (warps 2g,2g+1) owns rows 6g..6g+5.
// stage A: warp half h covers H-cols [64h,64h+64), 2/lane, all 6 rows.
// stage B: warp half h covers rows 6g+3h..6g+3h+2, all 64 D-cols, 2/lane.
__device__ __forceinline__ void feval(Smem* s, int g, int h, int l,
                                      const u64 (*Yind)[D_], float (*Kout)[D_]) {
    bar_pair(g);                           // pair's Yind writes visible
    const int rg0 = RPG * g;
    const int cA = 64 * h + 2 * l;

    // ---- stage A: Hd[:, cA..cA+1] = tanh(Yind @ W1 + b1), duplicated store ----
    u64 acc[RPG];
    {
        u64 bias = *(const u64*)&s->b1[cA];
        #pragma unroll
        for (int rr = 0; rr < RPG; rr++) acc[rr] = bias;
    }
    #pragma unroll 4
    for (int d0 = 0; d0 < D_; d0 += 4) {
        u64 wv[4];
        #pragma unroll
        for (int dd = 0; dd < 4; dd++)
            wv[dd] = *(const u64*)&s->W1[d0 + dd][cA];         // LDS.64 conflict-free
        #pragma unroll
        for (int rr = 0; rr < RPG; rr++) {
            ulonglong2 y01 = *(const ulonglong2*)&Yind[rg0 + rr][d0];     // {y0,y0},{y1,y1}
            ulonglong2 y23 = *(const ulonglong2*)&Yind[rg0 + rr][d0 + 2]; // broadcast LDS.128
            acc[rr] = ffma2(y01.x, wv[0], acc[rr]);
            acc[rr] = ffma2(y01.y, wv[1], acc[rr]);
            acc[rr] = ffma2(y23.x, wv[2], acc[rr]);
            acc[rr] = ffma2(y23.y, wv[3], acc[rr]);
        }
    }
    #pragma unroll
    for (int rr = 0; rr < RPG; rr++) {
        float2 v = u2f2(acc[rr]);
        ulonglong2 st;
        st.x = dup2(tanhf(v.x));
        st.y = dup2(tanhf(v.y));
        *(ulonglong2*)&s->Hd[rg0 + rr][cA] = st;               // STS.128 conflict-free
    }
    bar_pair(g);                           // pair's Hd writes visible

    // ---- stage B: Kout[rB, 2l..2l+1] = Hd @ W2 + b2 (plain store) ----
    const int rB0 = rg0 + RPB * h;
    u64 a2[RPB];
    {
        u64 bias2 = *(const u64*)&s->b2[2 * l];
        #pragma unroll
        for (int rr = 0; rr < RPB; rr++) a2[rr] = bias2;
    }
    #pragma unroll 4
    for (int j0 = 0; j0 < H_; j0 += 4) {
        u64 w2v[4];
        #pragma unroll
        for (int dd = 0; dd < 4; dd++)
            w2v[dd] = *(const u64*)&s->W2[j0 + dd][2 * l];     // LDS.64 conflict-free
        #pragma unroll
        for (int rr = 0; rr < RPB; rr++) {
            ulonglong2 h01 = *(const ulonglong2*)&s->Hd[rB0 + rr][j0];     // bc LDS.128
            ulonglong2 h23 = *(const ulonglong2*)&s->Hd[rB0 + rr][j0 + 2];
            a2[rr] = ffma2(h01.x, w2v[0], a2[rr]);
            a2[rr] = ffma2(h01.y, w2v[1], a2[rr]);
            a2[rr] = ffma2(h23.x, w2v[2], a2[rr]);
            a2[rr] = ffma2(h23.y, w2v[3], a2[rr]);
        }
    }
    #pragma unroll
    for (int rr = 0; rr < RPB; rr++) {
        float2 v = u2f2(a2[rr]);
        *(float2*)&Kout[rB0 + rr][2 * l] = v;                  // thread-local consumers
    }
}

// ---- Out(dup) = Y + dt * sum(cf[kk]*K[kk]) over this thread's rows/cols ----
template <int NK>
__device__ __forceinline__ void build_stage(Smem* s, int rB0, int l, float dtv,
                                            const float* cf, u64 (*Out)[D_]) {
    #pragma unroll
    for (int rr = 0; rr < RPB; rr++) {
        const int r = rB0 + rr;
        float ax = 0.f, ay = 0.f;
        #pragma unroll
        for (int kk = 0; kk < NK; kk++) {
            float2 kv = *(const float2*)&s->K[kk][r][2 * l];
            ax = fmaf(cf[kk], kv.x, ax);
            ay = fmaf(cf[kk], kv.y, ay);
        }
        ulonglong2 yq = *(const ulonglong2*)&s->Yd[r][2 * l];
        float vx = fmaf(dtv, ax, ulo(yq.x));
        float vy = fmaf(dtv, ay, ulo(yq.y));
        ulonglong2 st; st.x = dup2(vx); st.y = dup2(vy);
        *(ulonglong2*)&Out[r][2 * l] = st;
    }
}

// ---------------- persistent ODE solver kernel ----------------
__global__ void __launch_bounds__(TPB, 1)
ode_kernel(const float* __restrict__ first_point,
           const float* __restrict__ times,
           const float* __restrict__ gW1, const float* __restrict__ gb1,
           const float* __restrict__ gW2, const float* __restrict__ gb2,
           float* __restrict__ sol) {
    extern __shared__ char smem_raw[];
    Smem* s = (Smem*)smem_raw;

    const int tid = threadIdx.x;
    const int w = tid >> 5;
    const int l = tid & 31;
    const int g = w >> 1;
    const int h = w & 1;
    const int row0 = blockIdx.x * RPC;
    const int rB0 = RPG * g + RPB * h;     // this thread's 3 owned rows

    // load weights + initial state (Y duplicated)
    for (int i = tid; i < D_ * H_; i += TPB) ((float*)s->W1)[i] = gW1[i];
    for (int i = tid; i < H_ * D_; i += TPB) ((float*)s->W2)[i] = gW2[i];
    for (int i = tid; i < H_; i += TPB) s->b1[i] = gb1[i];
    for (int i = tid; i < D_; i += TPB) s->b2[i] = gb2[i];
    for (int i = tid; i < RPC * D_; i += TPB) {
        int row = i / D_, d = i % D_;
        s->Yd[row][d] = dup2(first_point[(size_t)row0 * D_ + i]);
    }
    __syncthreads();

    // sol at t index 0 (coalesced)
    #pragma unroll
    for (int rr = 0; rr < RPB; rr++) {
        const int r = rB0 + rr;
        float2 v = make_float2(ulo(s->Yd[r][2 * l]), ulo(s->Yd[r][2 * l + 1]));
        *(float2*)&sol[((size_t)(row0 + r) * T_ + 0) * D_ + 2 * l] = v;
    }

    // dopri5 coefficients
    const float C2[1] = {0.2f};
    const float C3[2] = {3.f / 40.f, 9.f / 40.f};
    const float C4[3] = {44.f / 45.f, -56.f / 15.f, 32.f / 9.f};
    const float C5[4] = {19372.f / 6561.f, -25360.f / 2187.f, 64448.f / 6561.f, -212.f / 729.f};
    const float C6[5] = {9017.f / 3168.f, -355.f / 33.f, 46732.f / 5247.f, 49.f / 176.f,
                         -5103.f / 18656.f};
    const float CB[6] = {35.f / 384.f, 0.f, 500.f / 1113.f, 125.f / 192.f,
                         -2187.f / 6784.f, 11.f / 84.f};
    const float E1 = 71.f / 57600.f, E3 = -71.f / 16695.f, E4 = 71.f / 1920.f;
    const float E5 = -17253.f / 339200.f, E6 = 22.f / 525.f, E7 = -1.f / 40.f;

    float t  = times[0];
    float dt = times[1] - times[0];
    int sc = 0;   // executed-step counter (uniform across CTAs)

    for (int ti = 0; ti < T_ - 1; ti++) {
        const float t_target = times[ti + 1];

        for (int iter = 0; iter < MAX_INNER; iter++) {
            const float remaining = t_target - t;
            if (remaining <= 0.0f) break;              // remaining iters are exact no-ops
            const float dt_try = fminf(dt, remaining);

            // 7 stages
            feval(s, g, h, l, s->Yd, s->K[0]);
            build_stage<1>(s, rB0, l, dt_try, C2, s->Ytd); feval(s, g, h, l, s->Ytd, s->K[1]);
            build_stage<2>(s, rB0, l, dt_try, C3, s->Ytd); feval(s, g, h, l, s->Ytd, s->K[2]);
            build_stage<3>(s, rB0, l, dt_try, C4, s->Ytd); feval(s, g, h, l, s->Ytd, s->K[3]);
            build_stage<4>(s, rB0, l, dt_try, C5, s->Ytd); feval(s, g, h, l, s->Ytd, s->K[4]);
            build_stage<5>(s, rB0, l, dt_try, C6, s->Ytd); feval(s, g, h, l, s->Ytd, s->K[5]);
            build_stage<6>(s, rB0, l, dt_try, CB, s->Y5d); feval(s, g, h, l, s->Y5d, s->K[6]);

            // local error accumulation over this thread's 3 rows x 2 cols
            float local = 0.f;
            #pragma unroll
            for (int rr = 0; rr < RPB; rr++) {
                const int r = rB0 + rr;
                ulonglong2 yq  = *(const ulonglong2*)&s->Yd[r][2 * l];
                ulonglong2 y5q = *(const ulonglong2*)&s->Y5d[r][2 * l];
                #pragma unroll
                for (int c = 0; c < 2; c++) {
                    const int d = 2 * l + c;
                    float e = E1 * s->K[0][r][d];
                    e = fmaf(E3, s->K[2][r][d], e);
                    e = fmaf(E4, s->K[3][r][d], e);
                    e = fmaf(E5, s->K[4][r][d], e);
                    e = fmaf(E6, s->K[5][r][d], e);
                    e = fmaf(E7, s->K[6][r][d], e);
                    e *= dt_try;
                    float yv  = (c == 0) ? ulo(yq.x)  : ulo(yq.y);
                    float y5v = (c == 0) ? ulo(y5q.x) : ulo(y5q.y);
                    float scale = ATOL_ + RTOL_ * fmaxf(fabsf(yv), fabsf(y5v));
                    float q = e / scale;
                    local = fmaf(q, q, local);
                }
            }

            // CTA reduction: warp shfl + one pass over the 8 warp sums
            #pragma unroll
            for (int off = 16; off > 0; off >>= 1)
                local += __shfl_xor_sync(0xffffffffu, local, off);
            if (l == 0) s->red[w] = local;
            __syncthreads();
            if (w == 0) {
                float v = (l < NW_) ? s->red[l] : 0.f;
                #pragma unroll
                for (int off = 4; off > 0; off >>= 1)
                    v += __shfl_xor_sync(0xffffffffu, v, off);
                if (l == 0) g_part[sc & 1][blockIdx.x] = v;
            }

            grid_barrier(tid);

            // global reduction of the 128 per-CTA partials (warp 0, L2 loads)
            if (w == 0) {
                const float* gp = g_part[sc & 1];
                float v = __ldcg(&gp[l]) + __ldcg(&gp[l + 32])
                        + __ldcg(&gp[l + 64]) + __ldcg(&gp[l + 96]);
                #pragma unroll
                for (int off = 16; off > 0; off >>= 1)
                    v += __shfl_xor_sync(0xffffffffu, v, off);
                if (l == 0) s->s_ratio = sqrtf(v / (float)NELEM);
            }
            __syncthreads();
            const float ratio = s->s_ratio;

            const bool accept = (ratio <= 1.0f);
            if (accept) {
                t = t + dt_try;
                #pragma unroll
                for (int rr = 0; rr < RPB; rr++) {
                    const int r = rB0 + rr;
                    *(ulonglong2*)&s->Yd[r][2 * l] =
                        *(const ulonglong2*)&s->Y5d[r][2 * l];   // thread-local
                }
            }
            float factor = 0.9f * powf(fmaxf(ratio, 1e-10f), -0.2f);
            factor = fminf(fmaxf(factor, 0.2f), 10.0f);
            dt = dt * factor;
            sc++;
        }

        t = t_target;   // snap to target (matches reference)

        // write accepted state for this interval (coalesced)
        #pragma unroll
        for (int rr = 0; rr < RPB; rr++) {
            const int r = rB0 + rr;
            float2 v = make_float2(ulo(s->Yd[r][2 * l]), ulo(s->Yd[r][2 * l + 1]));
            *(float2*)&sol[((size_t)(row0 + r) * T_ + (ti + 1)) * D_ + 2 * l] = v;
        }
    }
}

// ---------------- decode kernel: pred = sol_z @ Wo + bo ----------------
#define DEC_ROWS 32
__global__ void __launch_bounds__(256)
decode_kernel(const float* __restrict__ gWo, const float* __restrict__ gbo,
              const float* __restrict__ sol_src, float* __restrict__ pred_out) {
    __shared__ float sWo[D_][O_];        // 32 KB
    __shared__ float sbo[O_];
    __shared__ float sx[DEC_ROWS][D_];   // 8 KB

    const int tid = threadIdx.x;
    for (int i = tid; i < D_ * O_; i += 256) ((float*)sWo)[i] = gWo[i];
    for (int i = tid; i < O_; i += 256) sbo[i] = gbo[i];

    const size_t row0 = (size_t)blockIdx.x * DEC_ROWS;
    for (int i = tid; i < DEC_ROWS * D_; i += 256)
        ((float*)sx)[i] = sol_src[row0 * D_ + i];
    __syncthreads();

    const int w = tid >> 5;
    const int l = tid & 31;
    const int rb = w * 4;                // 8 warps x 4 rows = 32 rows

    u64 a0[4], a1[4];
    {
        const u64* bop = (const u64*)sbo;
        u64 i0 = bop[2 * l], i1 = bop[2 * l + 1];
        #pragma unroll
        for (int rr = 0; rr < 4; rr++) { a0[rr] = i0; a1[rr] = i1; }
    }
    #pragma unroll 4
    for (int d0 = 0; d0 < D_; d0 += 4) {
        ulonglong2 wq[4];
        #pragma unroll
        for (int dd = 0; dd < 4; dd++)
            wq[dd] = *(const ulonglong2*)&sWo[d0 + dd][4 * l];
        float4 xv[4];
        #pragma unroll
        for (int rr = 0; rr < 4; rr++)
            xv[rr] = *(const float4*)&sx[rb + rr][d0];
        #pragma unroll
        for (int dd = 0; dd < 4; dd++) {
            #pragma unroll
            for (int rr = 0; rr < 4; rr++) {
                float x = (dd == 0) ? xv[rr].x : (dd == 1) ? xv[rr].y
                        : (dd == 2) ? xv[rr].z : xv[rr].w;
                u64 xd = dup2(x);
                a0[rr] = ffma2(xd, wq[dd].x, a0[rr]);
                a1[rr] = ffma2(xd, wq[dd].y, a1[rr]);
            }
        }
    }
    #pragma unroll
    for (int rr = 0; rr < 4; rr++) {
        const size_t r = row0 + rb + rr;
        float2 lo = u2f2(a0[rr]), hi = u2f2(a1[rr]);
        *(float4*)&pred_out[r * O_ + 4 * l] = make_float4(lo.x, lo.y, hi.x, hi.y);
    }
}

// ---------------- launch ----------------
extern "C" void kernel_launch(void* const* d_in, const int* in_sizes, int n_in,
                              void* d_out, int out_size) {
    const float* first_point = (const float*)d_in[0];
    const float* times       = (const float*)d_in[1];
    const float* W1          = (const float*)d_in[2];
    const float* b1          = (const float*)d_in[3];
    const float* W2          = (const float*)d_in[4];
    const float* b2          = (const float*)d_in[5];
    const float* Wo          = (const float*)d_in[6];
    const float* bo          = (const float*)d_in[7];

    float* out = (float*)d_out;
    const long long NS = (long long)NROW * T_ * D_;   // 12,582,912 (sol_z)
    const long long NP = (long long)NROW * T_ * O_;   // 25,165,824 (pred_x)

    float* sol_dst;
    float* pred_out;
    if ((long long)out_size == NS + NP)      { sol_dst = out;  pred_out = out + NS; }
    else if ((long long)out_size == NP) {
        float* gsol_ptr = nullptr;
        cudaGetSymbolAddress((void**)&gsol_ptr, g_sol);
        sol_dst = gsol_ptr; pred_out = out;
    }
    else if ((long long)out_size == NS)      { sol_dst = out;  pred_out = nullptr; }
    else                                     { sol_dst = out;  pred_out = out + NS; }

    cudaFuncSetAttribute(ode_kernel, cudaFuncAttributeMaxDynamicSharedMemorySize, SMEM_BYTES);

    ode_kernel<<<NCTA, TPB, SMEM_BYTES>>>(first_point, times, W1, b1, W2, b2, sol_dst);

    if (pred_out)
        decode_kernel<<<(NROW * T_) / DEC_ROWS, 256>>>(Wo, bo, sol_dst, pred_out);
}